// round 11
// baseline (speedup 1.0000x reference)
#include <cuda_runtime.h>
#include <cuda_fp16.h>

// BilateralSlice: grid (4,12,8,16,16) f32, guide (4,1,1024,1024) f32,
// out (4,12,1024,1024) f32.
//
// R10 structure (one CTA = (b, 2 rows); fp16 z-pair smem slice; block-split
// pixels x = t, t+512; __stcs STG.32; 32-reg / 4 CTAs/SM) with R11 delta:
// TWO-STAGE staging. Raw grid rows y0/y1 for both output rows are loaded
// once with float4 LDG (each grid value read exactly once), then the
// y-lerped fp16 z-pair slice S is built from smem -> 16x fewer staging LDG
// instructions and half the staging L2 traffic.

#define NB 4
#define NC 12
#define DG 8
#define HG 16
#define WG 16
#define HH 1024
#define WW 1024

constexpr int XSTRIDE = 100;             // S words per x (96 + 4 pad)
constexpr int RSTRIDE = WG * XSTRIDE;    // 1600 S words per row slice
constexpr int ROWS    = 2;
constexpr int THREADS = 512;
constexpr int RAWY    = NC * DG * WG;    // 1536 floats per (row, yrow)

__global__ void __launch_bounds__(THREADS, 4)
bilateral_slice_kernel(const float* __restrict__ grid,
                       const float* __restrict__ guide,
                       float* __restrict__ out)
{
    __shared__ float        raw[2 * 2 * RAWY];    // [r][yr][c*128+z*16+x] 24.6KB
    __shared__ unsigned int S[ROWS * RSTRIDE];    // 3200 words = 12.8 KB

    const int b     = blockIdx.x >> 9;
    const int rg    = blockIdx.x & 511;
    const int ybase = rg * ROWS;
    const int tid   = threadIdx.x;

    // ---- prefetch guide for both rows/slots (overlaps staging latency) ----
    const float* gpix = guide + (size_t)b * (HH * WW) + (size_t)ybase * WW;
    float gvp[ROWS][2];
    #pragma unroll
    for (int r = 0; r < ROWS; ++r) {
        gvp[r][0] = __ldg(&gpix[(size_t)r * WW + tid]);
        gvp[r][1] = __ldg(&gpix[(size_t)r * WW + tid + THREADS]);
    }

    // ---- per-row y params ----
    int   y0r[ROWS], y1r[ROWS];
    float fyv[ROWS], wy0v[ROWS];
    #pragma unroll
    for (int r = 0; r < ROWS; ++r) {
        const float iyf = (float)(ybase + r) * (15.0f / 1023.0f);
        const float y0f = floorf(iyf);
        y0r[r]  = (int)y0f;
        y1r[r]  = min(y0r[r] + 1, HG - 1);
        fyv[r]  = iyf - y0f;
        wy0v[r] = 1.0f - fyv[r];
    }

    // ---- stage 1: raw grid rows, float4 LDG, each value read once ----
    const float4* gb4 = reinterpret_cast<const float4*>(
        grid + (size_t)b * (NC * DG * HG * WG));
    #pragma unroll
    for (int i = tid; i < 2 * 2 * (RAWY / 4); i += THREADS) {   // 1536 float4
        int r  = i >= 768;
        int j  = i - r * 768;
        int yr = j >= 384;
        int k  = j - yr * 384;           // c*32 + z*4 + x4
        int c  = k >> 5;
        int z  = (k >> 2) & 7;
        int x4 = k & 3;
        int yrow = yr ? y1r[r] : y0r[r];
        float4 v = gb4[(c * DG + z) * (HG * WG / 4) + yrow * (WG / 4) + x4];
        *reinterpret_cast<float4*>(&raw[i * 4]) = v;
    }
    __syncthreads();

    // ---- stage 2: build y-lerped fp16 z-pair slice from smem ----
    #pragma unroll
    for (int e = tid; e < ROWS * RAWY * 2; e += THREADS) {   // 3072 entries
        int r  = e >= RAWY * 2;
        int f  = e - r * (RAWY * 2);
        // f in [0, 3072): low bit selects nothing; reuse layout zc*16+x over
        // 1536 with f < 1536 handled by splitting: actually entries = 1536/row
        if (f < RAWY) {
            int x  = f & 15;
            int zc = f >> 4;             // z*12 + c
            int z  = zc / 12;
            int c  = zc - z * 12;
            int zb = min(z + 1, DG - 1);
            const float* r0p = &raw[(r * 2 + 0) * RAWY];
            const float* r1p = &raw[(r * 2 + 1) * RAWY];
            int ia = c * 128 + z  * 16 + x;
            int ib = c * 128 + zb * 16 + x;
            float va = wy0v[r] * r0p[ia] + fyv[r] * r1p[ia];
            float vb = wy0v[r] * r0p[ib] + fyv[r] * r1p[ib];
            __half2 h = __floats2half2_rn(va, vb);
            S[r * RSTRIDE + x * XSTRIDE + z * 12 + c] =
                *reinterpret_cast<unsigned int*>(&h);
        }
    }
    __syncthreads();

    float* obase = out + (size_t)b * NC * (size_t)(HH * WW)
                       + (size_t)ybase * WW;

    #pragma unroll
    for (int r = 0; r < ROWS; ++r) {
        #pragma unroll
        for (int s = 0; s < 2; ++s) {
            const int   x    = tid + s * THREADS;
            const float ixf  = (float)x * (15.0f / 1023.0f);
            const float x0f  = floorf(ixf);
            const int   x0   = (int)x0f;
            const float fx   = ixf - x0f;
            const int   xa   = x0 * XSTRIDE;
            const int   xbv  = min(x0 + 1, WG - 1) * XSTRIDE;
            const __half2 hwx0 = __float2half2_rn(1.0f - fx);
            const __half2 hwx1 = __float2half2_rn(fx);

            const float gv = gvp[r][s];
            float iz  = __saturatef(gv) * (float)(DG - 1);
            float z0f = floorf(iz);
            int   z0  = (int)z0f;
            float fz  = iz - z0f;
            const float wz0 = 1.0f - fz;
            const float wz1 = fz;

            const int zo = r * RSTRIDE + z0 * 12;
            const uint4* pa = reinterpret_cast<const uint4*>(&S[xa + zo]);
            const uint4* pb = reinterpret_cast<const uint4*>(&S[xbv + zo]);
            uint4 A0 = pa[0], A1 = pa[1], A2 = pa[2];
            uint4 B0 = pb[0], B1 = pb[1], B2 = pb[2];

            const unsigned int Aw[12] = {A0.x, A0.y, A0.z, A0.w,
                                         A1.x, A1.y, A1.z, A1.w,
                                         A2.x, A2.y, A2.z, A2.w};
            const unsigned int Bw[12] = {B0.x, B0.y, B0.z, B0.w,
                                         B1.x, B1.y, B1.z, B1.w,
                                         B2.x, B2.y, B2.z, B2.w};

            float* opix = obase + (size_t)r * WW + x;
            #pragma unroll
            for (int c = 0; c < NC; ++c) {
                __half2 a  = *reinterpret_cast<const __half2*>(&Aw[c]);
                __half2 bb = *reinterpret_cast<const __half2*>(&Bw[c]);
                __half2 t  = __hfma2(bb, hwx1, __hmul2(a, hwx0));
                float2  f  = __half22float2(t);
                __stcs(opix + (size_t)c * (HH * WW),
                       fmaf(wz0, f.x, wz1 * f.y));
            }
        }
    }
}

extern "C" void kernel_launch(void* const* d_in, const int* in_sizes, int n_in,
                              void* d_out, int out_size)
{
    const float* grid  = nullptr;
    const float* guide = nullptr;
    for (int i = 0; i < n_in; ++i) {
        if (in_sizes[i] == NB * NC * DG * HG * WG) grid  = (const float*)d_in[i];
        else if (in_sizes[i] == NB * HH * WW)      guide = (const float*)d_in[i];
    }

    dim3 gridDim(NB * HH / ROWS);   // 2048 CTAs: one per (batch, 2-row group)
    bilateral_slice_kernel<<<gridDim, THREADS>>>(grid, guide, (float*)d_out);
}

// round 12
// speedup vs baseline: 1.1083x; 1.1083x over previous
#include <cuda_runtime.h>
#include <cuda_fp16.h>

// BilateralSlice: grid (4,12,8,16,16) f32, guide (4,1,1024,1024) f32,
// out (4,12,1024,1024) f32.
//
// One CTA = (b, 2 rows); 32-reg / 4 CTAs/SM; block-split pixels (x=t, t+512);
// fp16 z-pair smem slice; __stcs STG.32 stores.
// R12 staging: stage 1 loads y0+y1 float4 pairs (each grid value read once
// from L2) and y-lerps IN REGISTERS, storing only the lerped row (12.3 KB).
// Stage 2: 768 vectorized trips build the z-paired fp16 slice
// (2x LDS.128 -> 4 cvt -> 4 STS.32), no predicated waste.

#define NB 4
#define NC 12
#define DG 8
#define HG 16
#define WG 16
#define HH 1024
#define WW 1024

constexpr int XSTRIDE = 100;             // S words per x (96 + 4 pad)
constexpr int RSTRIDE = WG * XSTRIDE;    // 1600 S words per row slice
constexpr int ROWS    = 2;
constexpr int THREADS = 512;
constexpr int RAWY    = NC * DG * WG;    // 1536 floats per lerped row

__global__ void __launch_bounds__(THREADS, 4)
bilateral_slice_kernel(const float* __restrict__ grid,
                       const float* __restrict__ guide,
                       float* __restrict__ out)
{
    __shared__ float        rawL[ROWS * RAWY];    // y-lerped rows, 12.3 KB
    __shared__ unsigned int S[ROWS * RSTRIDE];    // 3200 words = 12.8 KB

    const int b     = blockIdx.x >> 9;
    const int rg    = blockIdx.x & 511;
    const int ybase = rg * ROWS;
    const int tid   = threadIdx.x;

    // ---- prefetch guide for both rows/slots (overlaps staging latency) ----
    const float* gpix = guide + (size_t)b * (HH * WW) + (size_t)ybase * WW;
    float gvp[ROWS][2];
    #pragma unroll
    for (int r = 0; r < ROWS; ++r) {
        gvp[r][0] = __ldg(&gpix[(size_t)r * WW + tid]);
        gvp[r][1] = __ldg(&gpix[(size_t)r * WW + tid + THREADS]);
    }

    // ---- per-row y params ----
    int   y0r[ROWS], y1r[ROWS];
    float fyv[ROWS], wy0v[ROWS];
    #pragma unroll
    for (int r = 0; r < ROWS; ++r) {
        const float iyf = (float)(ybase + r) * (15.0f / 1023.0f);
        const float y0f = floorf(iyf);
        y0r[r]  = (int)y0f;
        y1r[r]  = min(y0r[r] + 1, HG - 1);
        fyv[r]  = iyf - y0f;
        wy0v[r] = 1.0f - fyv[r];
    }

    // ---- stage 1: load y0+y1 float4, y-lerp in registers, store lerped ----
    const float4* gb4 = reinterpret_cast<const float4*>(
        grid + (size_t)b * (NC * DG * HG * WG));
    #pragma unroll
    for (int i = tid; i < ROWS * (RAWY / 4); i += THREADS) {   // 768 trips
        int r  = i >= (RAWY / 4);
        int k  = i - r * (RAWY / 4);     // c*32 + z*4 + x4
        int c  = k >> 5;
        int z  = (k >> 2) & 7;
        int x4 = k & 3;
        int base = (c * DG + z) * (HG * WG / 4) + x4;
        float4 v0 = gb4[base + y0r[r] * (WG / 4)];
        float4 v1 = gb4[base + y1r[r] * (WG / 4)];
        float4 v;
        v.x = wy0v[r] * v0.x + fyv[r] * v1.x;
        v.y = wy0v[r] * v0.y + fyv[r] * v1.y;
        v.z = wy0v[r] * v0.z + fyv[r] * v1.z;
        v.w = wy0v[r] * v0.w + fyv[r] * v1.w;
        *reinterpret_cast<float4*>(&rawL[r * RAWY + c * 128 + z * 16 + x4 * 4]) = v;
    }
    __syncthreads();

    // ---- stage 2: build z-paired fp16 slice, vectorized over 4 x ----
    #pragma unroll
    for (int e = tid; e < ROWS * (RAWY / 4); e += THREADS) {   // 768 trips
        int r  = e >= (RAWY / 4);
        int k  = e - r * (RAWY / 4);     // zc*4 + xg
        int zc = k >> 2;                 // z*12 + c
        int xg = k & 3;
        int z  = zc / 12;
        int c  = zc - z * 12;
        int zb = min(z + 1, DG - 1);
        float4 a4 = *reinterpret_cast<const float4*>(
            &rawL[r * RAWY + c * 128 + z  * 16 + xg * 4]);
        float4 b4 = *reinterpret_cast<const float4*>(
            &rawL[r * RAWY + c * 128 + zb * 16 + xg * 4]);
        const float av[4] = {a4.x, a4.y, a4.z, a4.w};
        const float bv[4] = {b4.x, b4.y, b4.z, b4.w};
        #pragma unroll
        for (int j = 0; j < 4; ++j) {
            __half2 h = __floats2half2_rn(av[j], bv[j]);   // {v(z), v(z+1)}
            S[r * RSTRIDE + (xg * 4 + j) * XSTRIDE + z * 12 + c] =
                *reinterpret_cast<unsigned int*>(&h);
        }
    }
    __syncthreads();

    float* obase = out + (size_t)b * NC * (size_t)(HH * WW)
                       + (size_t)ybase * WW;

    #pragma unroll
    for (int r = 0; r < ROWS; ++r) {
        #pragma unroll
        for (int s = 0; s < 2; ++s) {
            const int   x    = tid + s * THREADS;
            const float ixf  = (float)x * (15.0f / 1023.0f);
            const float x0f  = floorf(ixf);
            const int   x0   = (int)x0f;
            const float fx   = ixf - x0f;
            const int   xa   = x0 * XSTRIDE;
            const int   xbv  = min(x0 + 1, WG - 1) * XSTRIDE;
            const __half2 hwx0 = __float2half2_rn(1.0f - fx);
            const __half2 hwx1 = __float2half2_rn(fx);

            const float gv = gvp[r][s];
            float iz  = __saturatef(gv) * (float)(DG - 1);
            float z0f = floorf(iz);
            int   z0  = (int)z0f;
            float fz  = iz - z0f;
            const float wz0 = 1.0f - fz;
            const float wz1 = fz;

            const int zo = r * RSTRIDE + z0 * 12;
            const uint4* pa = reinterpret_cast<const uint4*>(&S[xa + zo]);
            const uint4* pb = reinterpret_cast<const uint4*>(&S[xbv + zo]);
            uint4 A0 = pa[0], A1 = pa[1], A2 = pa[2];
            uint4 B0 = pb[0], B1 = pb[1], B2 = pb[2];

            const unsigned int Aw[12] = {A0.x, A0.y, A0.z, A0.w,
                                         A1.x, A1.y, A1.z, A1.w,
                                         A2.x, A2.y, A2.z, A2.w};
            const unsigned int Bw[12] = {B0.x, B0.y, B0.z, B0.w,
                                         B1.x, B1.y, B1.z, B1.w,
                                         B2.x, B2.y, B2.z, B2.w};

            float* opix = obase + (size_t)r * WW + x;
            #pragma unroll
            for (int c = 0; c < NC; ++c) {
                __half2 a  = *reinterpret_cast<const __half2*>(&Aw[c]);
                __half2 bb = *reinterpret_cast<const __half2*>(&Bw[c]);
                __half2 t  = __hfma2(bb, hwx1, __hmul2(a, hwx0));
                float2  f  = __half22float2(t);
                __stcs(opix + (size_t)c * (HH * WW),
                       fmaf(wz0, f.x, wz1 * f.y));
            }
        }
    }
}

extern "C" void kernel_launch(void* const* d_in, const int* in_sizes, int n_in,
                              void* d_out, int out_size)
{
    const float* grid  = nullptr;
    const float* guide = nullptr;
    for (int i = 0; i < n_in; ++i) {
        if (in_sizes[i] == NB * NC * DG * HG * WG) grid  = (const float*)d_in[i];
        else if (in_sizes[i] == NB * HH * WW)      guide = (const float*)d_in[i];
    }

    dim3 gridDim(NB * HH / ROWS);   // 2048 CTAs: one per (batch, 2-row group)
    bilateral_slice_kernel<<<gridDim, THREADS>>>(grid, guide, (float*)d_out);
}

// round 13
// speedup vs baseline: 1.1112x; 1.0026x over previous
#include <cuda_runtime.h>
#include <cuda_fp16.h>

// BilateralSlice: grid (4,12,8,16,16) f32, guide (4,1,1024,1024) f32,
// out (4,12,1024,1024) f32.
//
// One CTA = (b, 2 rows); 32-reg / 4 CTAs/SM; block-split pixels (x=t, t+512);
// fp16 z-pair smem slice; __stcs STG.32 stores.
// R13 staging: SINGLE fused stage. Thread k = c*32 + z*4 + x4 loads the
// y0/y1 float4 pair (each grid value read once), y-lerps in registers, gets
// the z+1 lerped float4 from lane+4 via __shfl_down_sync (warp covers one c,
// all z, all x4), packs 4 half2 z-pairs, stores directly to S. No rawL
// round-trip, one barrier, 12.8 KB smem.

#define NB 4
#define NC 12
#define DG 8
#define HG 16
#define WG 16
#define HH 1024
#define WW 1024

constexpr int XSTRIDE = 100;             // S words per x (96 + 4 pad)
constexpr int RSTRIDE = WG * XSTRIDE;    // 1600 S words per row slice
constexpr int ROWS    = 2;
constexpr int THREADS = 512;
constexpr int RAWY4   = (NC * DG * WG) / 4;   // 384 float4 per lerped row

__device__ __forceinline__ void stage_one(
    int i, const float4* __restrict__ gb4,
    const int* y0r, const int* y1r, const float* fyv, const float* wy0v,
    unsigned int* __restrict__ S)
{
    const int r  = i >= RAWY4;
    const int k  = i - r * RAWY4;        // c*32 + z*4 + x4
    const int c  = k >> 5;
    const int z  = (k >> 2) & 7;
    const int x4 = k & 3;

    const int base = (c * DG + z) * (HG * WG / 4) + x4;
    float4 v0 = gb4[base + y0r[r] * (WG / 4)];
    float4 v1 = gb4[base + y1r[r] * (WG / 4)];
    float4 v;
    v.x = wy0v[r] * v0.x + fyv[r] * v1.x;
    v.y = wy0v[r] * v0.y + fyv[r] * v1.y;
    v.z = wy0v[r] * v0.z + fyv[r] * v1.z;
    v.w = wy0v[r] * v0.w + fyv[r] * v1.w;

    // z+1 lerped values live in lane+4 (same c, same x4)
    float4 vn;
    vn.x = __shfl_down_sync(0xffffffffu, v.x, 4);
    vn.y = __shfl_down_sync(0xffffffffu, v.y, 4);
    vn.z = __shfl_down_sync(0xffffffffu, v.z, 4);
    vn.w = __shfl_down_sync(0xffffffffu, v.w, 4);
    if (z == DG - 1) vn = v;             // clamp z+1

    const float av[4] = {v.x,  v.y,  v.z,  v.w};
    const float bv[4] = {vn.x, vn.y, vn.z, vn.w};
    const int   sbase = r * RSTRIDE + z * 12 + c;
    #pragma unroll
    for (int j = 0; j < 4; ++j) {
        __half2 h = __floats2half2_rn(av[j], bv[j]);   // {v(z), v(z+1)}
        S[sbase + (x4 * 4 + j) * XSTRIDE] =
            *reinterpret_cast<unsigned int*>(&h);
    }
}

__global__ void __launch_bounds__(THREADS, 4)
bilateral_slice_kernel(const float* __restrict__ grid,
                       const float* __restrict__ guide,
                       float* __restrict__ out)
{
    __shared__ unsigned int S[ROWS * RSTRIDE];    // 3200 words = 12.8 KB

    const int b     = blockIdx.x >> 9;
    const int rg    = blockIdx.x & 511;
    const int ybase = rg * ROWS;
    const int tid   = threadIdx.x;

    // ---- prefetch guide for both rows/slots (overlaps staging latency) ----
    const float* gpix = guide + (size_t)b * (HH * WW) + (size_t)ybase * WW;
    float gvp[ROWS][2];
    #pragma unroll
    for (int r = 0; r < ROWS; ++r) {
        gvp[r][0] = __ldg(&gpix[(size_t)r * WW + tid]);
        gvp[r][1] = __ldg(&gpix[(size_t)r * WW + tid + THREADS]);
    }

    // ---- per-row y params ----
    int   y0r[ROWS], y1r[ROWS];
    float fyv[ROWS], wy0v[ROWS];
    #pragma unroll
    for (int r = 0; r < ROWS; ++r) {
        const float iyf = (float)(ybase + r) * (15.0f / 1023.0f);
        const float y0f = floorf(iyf);
        y0r[r]  = (int)y0f;
        y1r[r]  = min(y0r[r] + 1, HG - 1);
        fyv[r]  = iyf - y0f;
        wy0v[r] = 1.0f - fyv[r];
    }

    // ---- fused staging: two passes, every participating warp fully active
    const float4* gb4 = reinterpret_cast<const float4*>(
        grid + (size_t)b * (NC * DG * HG * WG));
    stage_one(tid, gb4, y0r, y1r, fyv, wy0v, S);             // i = 0..511
    if (tid < ROWS * RAWY4 - THREADS)                        // i = 512..767
        stage_one(tid + THREADS, gb4, y0r, y1r, fyv, wy0v, S);
    __syncthreads();

    float* obase = out + (size_t)b * NC * (size_t)(HH * WW)
                       + (size_t)ybase * WW;

    #pragma unroll
    for (int r = 0; r < ROWS; ++r) {
        #pragma unroll
        for (int s = 0; s < 2; ++s) {
            const int   x    = tid + s * THREADS;
            const float ixf  = (float)x * (15.0f / 1023.0f);
            const float x0f  = floorf(ixf);
            const int   x0   = (int)x0f;
            const float fx   = ixf - x0f;
            const int   xa   = x0 * XSTRIDE;
            const int   xbv  = min(x0 + 1, WG - 1) * XSTRIDE;
            const __half2 hwx0 = __float2half2_rn(1.0f - fx);
            const __half2 hwx1 = __float2half2_rn(fx);

            const float gv = gvp[r][s];
            float iz  = __saturatef(gv) * (float)(DG - 1);
            float z0f = floorf(iz);
            int   z0  = (int)z0f;
            float fz  = iz - z0f;
            const float wz0 = 1.0f - fz;
            const float wz1 = fz;

            const int zo = r * RSTRIDE + z0 * 12;
            const uint4* pa = reinterpret_cast<const uint4*>(&S[xa + zo]);
            const uint4* pb = reinterpret_cast<const uint4*>(&S[xbv + zo]);
            uint4 A0 = pa[0], A1 = pa[1], A2 = pa[2];
            uint4 B0 = pb[0], B1 = pb[1], B2 = pb[2];

            const unsigned int Aw[12] = {A0.x, A0.y, A0.z, A0.w,
                                         A1.x, A1.y, A1.z, A1.w,
                                         A2.x, A2.y, A2.z, A2.w};
            const unsigned int Bw[12] = {B0.x, B0.y, B0.z, B0.w,
                                         B1.x, B1.y, B1.z, B1.w,
                                         B2.x, B2.y, B2.z, B2.w};

            float* opix = obase + (size_t)r * WW + x;
            #pragma unroll
            for (int c = 0; c < NC; ++c) {
                __half2 a  = *reinterpret_cast<const __half2*>(&Aw[c]);
                __half2 bb = *reinterpret_cast<const __half2*>(&Bw[c]);
                __half2 t  = __hfma2(bb, hwx1, __hmul2(a, hwx0));
                float2  f  = __half22float2(t);
                __stcs(opix + (size_t)c * (HH * WW),
                       fmaf(wz0, f.x, wz1 * f.y));
            }
        }
    }
}

extern "C" void kernel_launch(void* const* d_in, const int* in_sizes, int n_in,
                              void* d_out, int out_size)
{
    const float* grid  = nullptr;
    const float* guide = nullptr;
    for (int i = 0; i < n_in; ++i) {
        if (in_sizes[i] == NB * NC * DG * HG * WG) grid  = (const float*)d_in[i];
        else if (in_sizes[i] == NB * HH * WW)      guide = (const float*)d_in[i];
    }

    dim3 gridDim(NB * HH / ROWS);   // 2048 CTAs: one per (batch, 2-row group)
    bilateral_slice_kernel<<<gridDim, THREADS>>>(grid, guide, (float*)d_out);
}